// round 16
// baseline (speedup 1.0000x reference)
#include <cuda_runtime.h>
#include <cuda_fp16.h>
#include <cstdint>

// Problem constants (fixed by reference setup_inputs)
#define D_MODEL 1024
#define HEAD    64
#define NHEAD   16
#define ROWS    16384   // B*S
#define NGRP    1024    // ROWS/NHEAD

// ---------------------------------------------------------------------------
// Scratch (device globals — no allocation allowed)
// ---------------------------------------------------------------------------
__device__ __align__(128) __half g_qp[ROWS * HEAD];   // f16 projections
__device__ __align__(128) __half g_kp[ROWS * HEAD];
__device__ __align__(128) __half g_vp[ROWS * HEAD];
__device__ __align__(128) __half g_x [NGRP * D_MODEL]; // f16, layout [n][i*16+h]

// f16 weights, transposed: [N, K=1024] (k-major rows). g_wp rows use permuted K.
__device__ __align__(128) __half g_wq[HEAD * D_MODEL];
__device__ __align__(128) __half g_wk[HEAD * D_MODEL];
__device__ __align__(128) __half g_wv[HEAD * D_MODEL];
__device__ __align__(128) __half g_wp[D_MODEL * D_MODEL];

// ---------------------------------------------------------------------------
// PTX helpers (sm_80 baseline features only — safe for compute_103 target)
// ---------------------------------------------------------------------------
__device__ __forceinline__ uint32_t smem_u32(const void* p) {
    uint32_t a;
    asm("{ .reg .u64 t; cvta.to.shared.u64 t, %1; cvt.u32.u64 %0, t; }" : "=r"(a) : "l"(p));
    return a;
}
__device__ __forceinline__ void mma_f16(float* d, const uint32_t* a, const uint32_t* b) {
    asm volatile(
        "mma.sync.aligned.m16n8k16.row.col.f32.f16.f16.f32 "
        "{%0,%1,%2,%3}, {%4,%5,%6,%7}, {%8,%9}, {%0,%1,%2,%3};\n"
        : "+f"(d[0]), "+f"(d[1]), "+f"(d[2]), "+f"(d[3])
        : "r"(a[0]), "r"(a[1]), "r"(a[2]), "r"(a[3]), "r"(b[0]), "r"(b[1]));
}
__device__ __forceinline__ void ldsm_x4(uint32_t* r, uint32_t addr) {
    asm volatile("ldmatrix.sync.aligned.m8n8.x4.shared.b16 {%0,%1,%2,%3}, [%4];"
                 : "=r"(r[0]), "=r"(r[1]), "=r"(r[2]), "=r"(r[3]) : "r"(addr));
}
__device__ __forceinline__ void ldsm_x4_t(uint32_t* r, uint32_t addr) {
    asm volatile("ldmatrix.sync.aligned.m8n8.x4.trans.shared.b16 {%0,%1,%2,%3}, [%4];"
                 : "=r"(r[0]), "=r"(r[1]), "=r"(r[2]), "=r"(r[3]) : "r"(addr));
}
__device__ __forceinline__ void cp_async16(uint32_t dst, const void* src) {
    asm volatile("cp.async.cg.shared.global [%0], [%1], 16;" :: "r"(dst), "l"(src));
}
#define CP_COMMIT() asm volatile("cp.async.commit_group;")
#define CP_WAIT0()  asm volatile("cp.async.wait_group 0;" ::: "memory")
#define CP_WAIT1()  asm volatile("cp.async.wait_group 1;" ::: "memory")

__device__ __forceinline__ uint32_t f16pack(float x, float y) {
    __half2 h = __floats2half2_rn(x, y);
    return *reinterpret_cast<uint32_t*>(&h);
}

// ---------------------------------------------------------------------------
// Weight prep, tight grid (32, 38): y<32 -> Wp tile (x, y) with K-permutation;
// y>=32 -> Q/K/V: q=(y-32), weight=q>>1, n-tile=q&1, k-tile=x.
// ---------------------------------------------------------------------------
__device__ __forceinline__
void wprep_qkv_tile(const float* __restrict__ W, __half* __restrict__ Bt,
                    int n0, int k0)
{
    __shared__ float t[32][33];
    const int tx = threadIdx.x, ty = threadIdx.y;
#pragma unroll
    for (int j = 0; j < 4; j++)
        t[ty + 8 * j][tx] = W[(size_t)(k0 + ty + 8 * j) * HEAD + n0 + tx];
    __syncthreads();
#pragma unroll
    for (int j = 0; j < 4; j++) {
        size_t o = (size_t)(n0 + ty + 8 * j) * 1024 + k0 + tx;
        Bt[o] = __float2half_rn(t[tx][ty + 8 * j]);
    }
}
__global__ __launch_bounds__(256)
void wprep_all_kernel(const float* W0, __half* B0, const float* W1, __half* B1,
                      const float* W2, __half* B2, const float* Wp, __half* Bp)
{
    const int tx = threadIdx.x, ty = threadIdx.y;
    if (blockIdx.y >= 32) {
        int q = blockIdx.y - 32;            // 0..5
        int n0 = (q & 1) * 32, k0 = blockIdx.x * 32;
        if ((q >> 1) == 0)      wprep_qkv_tile(W0, B0, n0, k0);
        else if ((q >> 1) == 1) wprep_qkv_tile(W1, B1, n0, k0);
        else                    wprep_qkv_tile(W2, B2, n0, k0);
        return;
    }
    // Wp with K-permutation: Bt[n][k'] = Wp[k][n], k' = (k&63)*16 + (k>>6)
    __shared__ float t[32][33];
    const int n0 = blockIdx.x * 32, kp0 = blockIdx.y * 32;
#pragma unroll
    for (int j = 0; j < 4; j++) {
        int l = ty + 8 * j;
        int kpr = kp0 + l;                          // k' index
        int k = (kpr & 15) * 64 + (kpr >> 4);       // original k = h*64+i
        t[l][tx] = Wp[(size_t)k * 1024 + n0 + tx];
    }
    __syncthreads();
#pragma unroll
    for (int j = 0; j < 4; j++) {
        size_t o = (size_t)(n0 + ty + 8 * j) * 1024 + kp0 + tx;
        Bp[o] = __float2half_rn(t[tx][ty + 8 * j]);
    }
}

// ---------------------------------------------------------------------------
// GEMM tile config: BM=128, BN=64, BK=64, 256 threads = 8 warps (4M x 2N),
// warp tile 32x32 (8 MMAs per k-step per warp, MMA:LDSM = 2:1).
// ---------------------------------------------------------------------------
#define PADK 72                         // f16 elems per smem row (144 B)
#define OFF_A  0
#define OFF_B  (128 * PADK)
#define STAGE_ELEMS (192 * PADK)        // 13824 halves = 27648 B
#define SM_BYTES_PROJ (2 * STAGE_ELEMS * 2)  // 55296 (proj: 2 stages, R12 schedule)
#define SM_BYTES_OUT  (3 * STAGE_ELEMS * 2)  // 82944 (out: 3-stage ring)

// ---- Projection GEMM (R12 schedule): A fp32 -> f16 on the fly, C f16 -------
struct PArgs {
    const float* A;
    const __half* B;
    const float* bias;
    __half* C;
};

__device__ __forceinline__
void gemm_proj_body(const PArgs& g, int ldc, int bm, __half* sm)
{
    const uint32_t sb = smem_u32(sm);
    const int tid  = threadIdx.x;
    const int lane = tid & 31, w = tid >> 5;
    const int gq = lane >> 2, tq = lane & 3;
    const int wm = (w >> 1) * 32, wn = (w & 1) * 32;

    const int rowA  = (lane & 15);
    const int colA8 = (lane >> 4) * 8;
    const int rowB  = ((lane >> 4) & 1) * 8 + (lane & 7);
    const int colB8 = ((lane >> 3) & 1) * 8;

    float acc[2][4][4];
#pragma unroll
    for (int mt = 0; mt < 2; mt++)
#pragma unroll
        for (int nt = 0; nt < 4; nt++)
#pragma unroll
            for (int r = 0; r < 4; r++) acc[mt][nt][r] = 0.f;

    float4 aR[8];

    auto load_A_regs = [&](int ch) {
        const int k0 = ch * 64;
#pragma unroll
        for (int p = 0; p < 8; p++) {
            int idx = p * 256 + tid;
            int r = idx >> 4, c4 = idx & 15;
            aR[p] = *(const float4*)&g.A[(size_t)(bm + r) * 1024 + k0 + c4 * 4];
        }
    };
    auto store_A = [&](int stg) {
        __half* A = sm + stg * STAGE_ELEMS + OFF_A;
#pragma unroll
        for (int p = 0; p < 8; p++) {
            int idx = p * 256 + tid;
            int r = idx >> 4, c4 = idx & 15;
            uint32_t h01 = f16pack(aR[p].x, aR[p].y);
            uint32_t h23 = f16pack(aR[p].z, aR[p].w);
            *(uint2*)(A + r * PADK + c4 * 4) = make_uint2(h01, h23);
        }
    };
    auto cp_B = [&](int ch, int stg) {
        const int k0 = ch * 64;
        const uint32_t bd = sb + (stg * STAGE_ELEMS + OFF_B) * 2;
#pragma unroll
        for (int p = 0; p < 2; p++) {
            int idx = p * 256 + tid;
            int r = idx >> 3, c8 = idx & 7;
            size_t off = (size_t)r * 1024 + k0 + c8 * 8;
            cp_async16(bd + (uint32_t)(r * 144 + c8 * 16), g.B + off);
        }
        CP_COMMIT();
    };
    auto do_mma = [&](int stg) {
        const uint32_t base = sb + (stg * STAGE_ELEMS) * 2;
        const uint32_t aB = base + OFF_A * 2;
        const uint32_t bB = base + OFF_B * 2;
#pragma unroll
        for (int ks = 0; ks < 4; ks++) {
            const int kk = ks * 16;
            uint32_t ah[2][4], bh[4][2];
#pragma unroll
            for (int mt = 0; mt < 2; mt++)
                ldsm_x4(ah[mt], aB + (uint32_t)((wm + mt * 16 + rowA) * 144 + (kk + colA8) * 2));
#pragma unroll
            for (int p = 0; p < 2; p++) {
                uint32_t rh[4];
                ldsm_x4(rh, bB + (uint32_t)((wn + p * 16 + rowB) * 144 + (kk + colB8) * 2));
                bh[2 * p][0] = rh[0]; bh[2 * p][1] = rh[1];
                bh[2 * p + 1][0] = rh[2]; bh[2 * p + 1][1] = rh[3];
            }
#pragma unroll
            for (int mt = 0; mt < 2; mt++)
#pragma unroll
                for (int nt = 0; nt < 4; nt++)
                    mma_f16(acc[mt][nt], ah[mt], bh[nt]);
        }
    };

    // R12 schedule: issue next chunk's loads BEFORE this chunk's MMAs.
    load_A_regs(0);
    cp_B(0, 0);
    store_A(0);
    CP_WAIT0();
    __syncthreads();

    for (int ch = 0; ch < 16; ch++) {
        const int cur = ch & 1;
        if (ch < 15) {
            cp_B(ch + 1, cur ^ 1);
            load_A_regs(ch + 1);
        }
        do_mma(cur);
        if (ch < 15) {
            store_A(cur ^ 1);
            CP_WAIT0();
        }
        __syncthreads();
    }

    // epilogue: bias + f16 store
#pragma unroll
    for (int mt = 0; mt < 2; mt++) {
        const int row0 = bm + wm + mt * 16 + gq;
#pragma unroll
        for (int nt = 0; nt < 4; nt++) {
            const int col = wn + nt * 8 + tq * 2;
            const float b0 = __ldg(&g.bias[col]);
            const float b1 = __ldg(&g.bias[col + 1]);
            *(uint32_t*)&g.C[(size_t)row0 * ldc + col] =
                f16pack(acc[mt][nt][0] + b0, acc[mt][nt][1] + b1);
            *(uint32_t*)&g.C[(size_t)(row0 + 8) * ldc + col] =
                f16pack(acc[mt][nt][2] + b0, acc[mt][nt][3] + b1);
        }
    }
}

__global__ __launch_bounds__(256)
void gemm3_kernel(PArgs p0, PArgs p1, PArgs p2, int ldc)
{
    extern __shared__ __half sm[];
    PArgs p = (blockIdx.z == 0) ? p0 : (blockIdx.z == 1) ? p1 : p2;
    gemm_proj_body(p, ldc, blockIdx.x * 128, sm);
}

// ---- Output GEMM: A f16, B f16, 3-stage cp.async ring, C fp32 + bias -------
__global__ __launch_bounds__(256)
void gemm_out_kernel(const __half* __restrict__ A, const __half* __restrict__ B,
                     const float* __restrict__ bias, float* __restrict__ C, int ldc)
{
    extern __shared__ __half sm[];
    const uint32_t sb = smem_u32(sm);
    const int tid  = threadIdx.x;
    const int lane = tid & 31, w = tid >> 5;
    const int gq = lane >> 2, tq = lane & 3;
    const int wm = (w >> 1) * 32, wn = (w & 1) * 32;
    const int bm = blockIdx.x * 128, bn = blockIdx.y * 64;

    const int rowA  = (lane & 15);
    const int colA8 = (lane >> 4) * 8;
    const int rowB  = ((lane >> 4) & 1) * 8 + (lane & 7);
    const int colB8 = ((lane >> 3) & 1) * 8;

    float acc[2][4][4];
#pragma unroll
    for (int mt = 0; mt < 2; mt++)
#pragma unroll
        for (int nt = 0; nt < 4; nt++)
#pragma unroll
            for (int r = 0; r < 4; r++) acc[mt][nt][r] = 0.f;

    auto cp_stage = [&](int ch, int stg) {
        const int k0 = ch * 64;
        const uint32_t ad = sb + (stg * STAGE_ELEMS + OFF_A) * 2;
        const uint32_t bd = sb + (stg * STAGE_ELEMS + OFF_B) * 2;
#pragma unroll
        for (int p = 0; p < 4; p++) {       // A: 128 rows x 8 segs
            int idx = p * 256 + tid;
            int r = idx >> 3, c8 = idx & 7;
            cp_async16(ad + (uint32_t)(r * 144 + c8 * 16),
                       A + (size_t)(bm + r) * 1024 + k0 + c8 * 8);
        }
#pragma unroll
        for (int p = 0; p < 2; p++) {       // B: 64 rows x 8 segs
            int idx = p * 256 + tid;
            int r = idx >> 3, c8 = idx & 7;
            cp_async16(bd + (uint32_t)(r * 144 + c8 * 16),
                       B + (size_t)(bn + r) * 1024 + k0 + c8 * 8);
        }
        CP_COMMIT();
    };
    auto do_mma = [&](int stg) {
        const uint32_t base = sb + (stg * STAGE_ELEMS) * 2;
        const uint32_t aB = base + OFF_A * 2;
        const uint32_t bB = base + OFF_B * 2;
#pragma unroll
        for (int ks = 0; ks < 4; ks++) {
            const int kk = ks * 16;
            uint32_t ah[2][4], bh[4][2];
#pragma unroll
            for (int mt = 0; mt < 2; mt++)
                ldsm_x4(ah[mt], aB + (uint32_t)((wm + mt * 16 + rowA) * 144 + (kk + colA8) * 2));
#pragma unroll
            for (int p = 0; p < 2; p++) {
                uint32_t rh[4];
                ldsm_x4(rh, bB + (uint32_t)((wn + p * 16 + rowB) * 144 + (kk + colB8) * 2));
                bh[2 * p][0] = rh[0]; bh[2 * p][1] = rh[1];
                bh[2 * p + 1][0] = rh[2]; bh[2 * p + 1][1] = rh[3];
            }
#pragma unroll
            for (int mt = 0; mt < 2; mt++)
#pragma unroll
                for (int nt = 0; nt < 4; nt++)
                    mma_f16(acc[mt][nt], ah[mt], bh[nt]);
        }
    };

    // 3-stage ring: two chunks in flight at all times.
    cp_stage(0, 0);
    cp_stage(1, 1);

    for (int ch = 0; ch < 16; ch++) {
        CP_WAIT1();          // stage ch complete (<=1 group pending)
        __syncthreads();     // all warps done reading slot (ch-1)%3
        if (ch + 2 < 16) cp_stage(ch + 2, (ch + 2) % 3);
        else             CP_COMMIT();
        do_mma(ch % 3);
    }

#pragma unroll
    for (int mt = 0; mt < 2; mt++) {
        const int row0 = bm + wm + mt * 16 + gq;
#pragma unroll
        for (int nt = 0; nt < 4; nt++) {
            const int col = bn + wn + nt * 8 + tq * 2;
            const float b0 = __ldg(&bias[col]);
            const float b1 = __ldg(&bias[col + 1]);
            float2 v0 = make_float2(acc[mt][nt][0] + b0, acc[mt][nt][1] + b1);
            float2 v1 = make_float2(acc[mt][nt][2] + b0, acc[mt][nt][3] + b1);
            *(float2*)&C[(size_t)row0 * ldc + col]       = v0;
            *(float2*)&C[(size_t)(row0 + 8) * ldc + col] = v1;
        }
    }
}

// ---------------------------------------------------------------------------
// Tensor-core attention. One CTA (128 thr, 4 warps) per group n.
// Q/K/V stored ROW-MAJOR (coalesced); transposed fragments via ldmatrix.trans.
//   S = 0.25 * Qg^T Kg (64x64, K=16), masked, f16; X'[n][i*16+h] = (S @ Vg^T)[i,h]
// ---------------------------------------------------------------------------
#define AT_STR 72     // row stride in halves for all attn smem tiles

__global__ __launch_bounds__(128)
void attn_kernel(const __half* __restrict__ qp, const __half* __restrict__ kp,
                 const __half* __restrict__ vp, const int* __restrict__ mask,
                 __half* __restrict__ X)
{
    __shared__ __align__(16) __half Qs[16 * AT_STR];  // Qs[hh][i]
    __shared__ __align__(16) __half Ks[16 * AT_STR];  // Ks[hh][j]
    __shared__ __align__(16) __half Vs[16 * AT_STR];  // Vs[h][j]
    __shared__ __align__(16) __half Ss[64 * AT_STR];  // S f16, row-major [i][j]

    const int n = blockIdx.x, tid = threadIdx.x;
    const int lane = tid & 31, w = tid >> 5;
    const int gq = lane >> 2, tq = lane & 3;

    const uint4* qg = (const uint4*)(qp + (size_t)n * NHEAD * HEAD);
    const uint4* kg = (const uint4*)(kp + (size_t)n * NHEAD * HEAD);
    const uint4* vg = (const uint4*)(vp + (size_t)n * NHEAD * HEAD);

    // Row-major coalesced loads: thread tid -> row hh = tid>>3, cols c0..c0+7
    {
        const int hh = tid >> 3, c0 = (tid & 7) * 8;
        *(uint4*)&Qs[hh * AT_STR + c0] = qg[tid];
        *(uint4*)&Ks[hh * AT_STR + c0] = kg[tid];
        *(uint4*)&Vs[hh * AT_STR + c0] = vg[tid];
    }
    __syncthreads();

    // ---- Stage 1: S rows [16w, 16w+16), all 64 cols; K = 16 (one k-step)
    const int rTA = (lane & 7) + ((lane >> 4) & 1) * 8;   // hh
    const int cTA = ((lane >> 3) & 1) * 8;                // i offset within warp tile
    const uint32_t qsB = smem_u32(Qs), ksB = smem_u32(Ks);
    uint32_t aQ[4];
    ldsm_x4_t(aQ, qsB + (uint32_t)(rTA * AT_STR + 16 * w + cTA) * 2);

    const int rTB = (lane & 7) + ((lane >> 3) & 1) * 8;   // hh
    const int cTB = (lane >> 4) * 8;                      // j offset

    float sacc[8][4];
#pragma unroll
    for (int nt = 0; nt < 8; nt++)
#pragma unroll
        for (int r = 0; r < 4; r++) sacc[nt][r] = 0.f;

#pragma unroll
    for (int p = 0; p < 4; p++) {
        uint32_t rb[4];
        ldsm_x4_t(rb, ksB + (uint32_t)(rTB * AT_STR + p * 16 + cTB) * 2);
        uint32_t b0[2] = {rb[0], rb[1]}, b1[2] = {rb[2], rb[3]};
        mma_f16(sacc[2 * p],     aQ, b0);
        mma_f16(sacc[2 * p + 1], aQ, b1);
    }

    // scale + mask + f16 store to Ss
    const int i0 = 16 * w + gq;
#pragma unroll
    for (int nt = 0; nt < 8; nt++) {
        const int j0 = nt * 8 + tq * 2;
        int2 m0 = *(const int2*)&mask[i0 * 64 + j0];
        int2 m1 = *(const int2*)&mask[(i0 + 8) * 64 + j0];
        float s0 = sacc[nt][0] * 0.25f; if (m0.x == 0) s0 = -1e30f;
        float s1 = sacc[nt][1] * 0.25f; if (m0.y == 0) s1 = -1e30f;
        float s2 = sacc[nt][2] * 0.25f; if (m1.x == 0) s2 = -1e30f;
        float s3 = sacc[nt][3] * 0.25f; if (m1.y == 0) s3 = -1e30f;
        *(uint32_t*)&Ss[i0 * AT_STR + j0]       = f16pack(s0, s1);
        *(uint32_t*)&Ss[(i0 + 8) * AT_STR + j0] = f16pack(s2, s3);
    }
    __syncthreads();

    // ---- Stage 2: X rows [16w, 16w+16) x 16 heads; K = 64 (4 k-steps)
    const int rowA  = (lane & 15);
    const int colA8 = (lane >> 4) * 8;
    const int rowB  = ((lane >> 4) & 1) * 8 + (lane & 7);
    const int colB8 = ((lane >> 3) & 1) * 8;
    const uint32_t ssB = smem_u32(Ss), vsB = smem_u32(Vs);
    float xacc[2][4];
#pragma unroll
    for (int nt = 0; nt < 2; nt++)
#pragma unroll
        for (int r = 0; r < 4; r++) xacc[nt][r] = 0.f;

#pragma unroll
    for (int ks = 0; ks < 4; ks++) {
        uint32_t aS[4], rb[4];
        ldsm_x4(aS, ssB + (uint32_t)((16 * w + rowA) * AT_STR + ks * 16 + colA8) * 2);
        ldsm_x4(rb, vsB + (uint32_t)(rowB * AT_STR + ks * 16 + colB8) * 2);
        uint32_t b0[2] = {rb[0], rb[1]}, b1[2] = {rb[2], rb[3]};
        mma_f16(xacc[0], aS, b0);
        mma_f16(xacc[1], aS, b1);
    }

    // X'[n][i*16 + h], f16 (pairs over consecutive h)
    __half* Xn = X + (size_t)n * D_MODEL;
#pragma unroll
    for (int nt = 0; nt < 2; nt++) {
        const int h0 = nt * 8 + tq * 2;
        *(uint32_t*)&Xn[i0 * 16 + h0]       = f16pack(xacc[nt][0], xacc[nt][1]);
        *(uint32_t*)&Xn[(i0 + 8) * 16 + h0] = f16pack(xacc[nt][2], xacc[nt][3]);
    }
}

// ---------------------------------------------------------------------------
extern "C" void kernel_launch(void* const* d_in, const int* in_sizes, int n_in,
                              void* d_out, int out_size)
{
    const float* query = (const float*)d_in[0];
    const float* key   = (const float*)d_in[1];
    const float* value = (const float*)d_in[2];
    const int*   mask  = (const int*)  d_in[3];
    const float* Wq    = (const float*)d_in[4];
    const float* bq    = (const float*)d_in[5];
    const float* Wk    = (const float*)d_in[6];
    const float* bk    = (const float*)d_in[7];
    const float* Wv    = (const float*)d_in[8];
    const float* bv    = (const float*)d_in[9];
    const float* Wp    = (const float*)d_in[10];
    const float* bp    = (const float*)d_in[11];
    float* out = (float*)d_out;

    __half *qp, *kp, *vp, *xg, *wq, *wk, *wv, *wp;
    cudaGetSymbolAddress((void**)&qp, g_qp);
    cudaGetSymbolAddress((void**)&kp, g_kp);
    cudaGetSymbolAddress((void**)&vp, g_vp);
    cudaGetSymbolAddress((void**)&xg, g_x);
    cudaGetSymbolAddress((void**)&wq, g_wq);
    cudaGetSymbolAddress((void**)&wk, g_wk);
    cudaGetSymbolAddress((void**)&wv, g_wv);
    cudaGetSymbolAddress((void**)&wp, g_wp);

    cudaFuncSetAttribute(gemm3_kernel, cudaFuncAttributeMaxDynamicSharedMemorySize, SM_BYTES_PROJ);
    cudaFuncSetAttribute(gemm_out_kernel, cudaFuncAttributeMaxDynamicSharedMemorySize, SM_BYTES_OUT);

    // Weight prep: tight merged grid (y<32: Wp, y>=32: Q/K/V tiles)
    wprep_all_kernel<<<dim3(32, 38), dim3(32, 8)>>>(Wq, wq, Wk, wk, Wv, wv, Wp, wp);

    // Merged projections: (16384 x 1024) @ (1024 x 64) + bias, x3 -> f16
    PArgs pq = {query, wq, bq, qp};
    PArgs pk = {key,   wk, bk, kp};
    PArgs pv = {value, wv, bv, vp};
    gemm3_kernel<<<dim3(ROWS / 128, 1, 3), 256, SM_BYTES_PROJ>>>(pq, pk, pv, HEAD);

    // Attention middle stage -> X' f16 [n][i*16+h]
    attn_kernel<<<NGRP, 128>>>(qp, kp, vp, mask, xg);

    // Output projection: (1024 x 1024) @ (1024 x 1024) + bias (fp32 out)
    gemm_out_kernel<<<dim3(NGRP / 128, D_MODEL / 64), 256, SM_BYTES_OUT>>>(xg, wp, bp, out, D_MODEL);
}

// round 17
// speedup vs baseline: 1.0710x; 1.0710x over previous
#include <cuda_runtime.h>
#include <cuda_fp16.h>
#include <cstdint>

// Problem constants (fixed by reference setup_inputs)
#define D_MODEL 1024
#define HEAD    64
#define NHEAD   16
#define ROWS    16384   // B*S
#define NGRP    1024    // ROWS/NHEAD

// ---------------------------------------------------------------------------
// Scratch (device globals — no allocation allowed)
// ---------------------------------------------------------------------------
__device__ __align__(128) __half g_qp[ROWS * HEAD];   // f16 projections
__device__ __align__(128) __half g_kp[ROWS * HEAD];
__device__ __align__(128) __half g_vp[ROWS * HEAD];
__device__ __align__(128) __half g_x [NGRP * D_MODEL]; // f16, layout [n][i*16+h]

// f16 weights, transposed: [N, K=1024] (k-major rows). g_wp rows use permuted K.
__device__ __align__(128) __half g_wq[HEAD * D_MODEL];
__device__ __align__(128) __half g_wk[HEAD * D_MODEL];
__device__ __align__(128) __half g_wv[HEAD * D_MODEL];
__device__ __align__(128) __half g_wp[D_MODEL * D_MODEL];

// ---------------------------------------------------------------------------
// PTX helpers (sm_80 baseline features only — safe for compute_103 target)
// ---------------------------------------------------------------------------
__device__ __forceinline__ uint32_t smem_u32(const void* p) {
    uint32_t a;
    asm("{ .reg .u64 t; cvta.to.shared.u64 t, %1; cvt.u32.u64 %0, t; }" : "=r"(a) : "l"(p));
    return a;
}
__device__ __forceinline__ void mma_f16(float* d, const uint32_t* a, const uint32_t* b) {
    asm volatile(
        "mma.sync.aligned.m16n8k16.row.col.f32.f16.f16.f32 "
        "{%0,%1,%2,%3}, {%4,%5,%6,%7}, {%8,%9}, {%0,%1,%2,%3};\n"
        : "+f"(d[0]), "+f"(d[1]), "+f"(d[2]), "+f"(d[3])
        : "r"(a[0]), "r"(a[1]), "r"(a[2]), "r"(a[3]), "r"(b[0]), "r"(b[1]));
}
__device__ __forceinline__ void ldsm_x4(uint32_t* r, uint32_t addr) {
    asm volatile("ldmatrix.sync.aligned.m8n8.x4.shared.b16 {%0,%1,%2,%3}, [%4];"
                 : "=r"(r[0]), "=r"(r[1]), "=r"(r[2]), "=r"(r[3]) : "r"(addr));
}
__device__ __forceinline__ void ldsm_x4_t(uint32_t* r, uint32_t addr) {
    asm volatile("ldmatrix.sync.aligned.m8n8.x4.trans.shared.b16 {%0,%1,%2,%3}, [%4];"
                 : "=r"(r[0]), "=r"(r[1]), "=r"(r[2]), "=r"(r[3]) : "r"(addr));
}
__device__ __forceinline__ void cp_async16(uint32_t dst, const void* src) {
    asm volatile("cp.async.cg.shared.global [%0], [%1], 16;" :: "r"(dst), "l"(src));
}
#define CP_COMMIT() asm volatile("cp.async.commit_group;")
#define CP_WAIT0()  asm volatile("cp.async.wait_group 0;" ::: "memory")
#define CP_WAIT1()  asm volatile("cp.async.wait_group 1;" ::: "memory")

__device__ __forceinline__ uint32_t f16pack(float x, float y) {
    __half2 h = __floats2half2_rn(x, y);
    return *reinterpret_cast<uint32_t*>(&h);
}

// ---------------------------------------------------------------------------
// Weight prep, tight grid (32, 38): y<32 -> Wp tile (x, y) with K-permutation;
// y>=32 -> Q/K/V: q=(y-32), weight=q>>1, n-tile=q&1, k-tile=x.
// ---------------------------------------------------------------------------
__device__ __forceinline__
void wprep_qkv_tile(const float* __restrict__ W, __half* __restrict__ Bt,
                    int n0, int k0)
{
    __shared__ float t[32][33];
    const int tx = threadIdx.x, ty = threadIdx.y;
#pragma unroll
    for (int j = 0; j < 4; j++)
        t[ty + 8 * j][tx] = W[(size_t)(k0 + ty + 8 * j) * HEAD + n0 + tx];
    __syncthreads();
#pragma unroll
    for (int j = 0; j < 4; j++) {
        size_t o = (size_t)(n0 + ty + 8 * j) * 1024 + k0 + tx;
        Bt[o] = __float2half_rn(t[tx][ty + 8 * j]);
    }
}
__global__ __launch_bounds__(256)
void wprep_all_kernel(const float* W0, __half* B0, const float* W1, __half* B1,
                      const float* W2, __half* B2, const float* Wp, __half* Bp)
{
    const int tx = threadIdx.x, ty = threadIdx.y;
    if (blockIdx.y >= 32) {
        int q = blockIdx.y - 32;            // 0..5
        int n0 = (q & 1) * 32, k0 = blockIdx.x * 32;
        if ((q >> 1) == 0)      wprep_qkv_tile(W0, B0, n0, k0);
        else if ((q >> 1) == 1) wprep_qkv_tile(W1, B1, n0, k0);
        else                    wprep_qkv_tile(W2, B2, n0, k0);
        return;
    }
    // Wp with K-permutation: Bt[n][k'] = Wp[k][n], k' = (k&63)*16 + (k>>6)
    __shared__ float t[32][33];
    const int n0 = blockIdx.x * 32, kp0 = blockIdx.y * 32;
#pragma unroll
    for (int j = 0; j < 4; j++) {
        int l = ty + 8 * j;
        int kpr = kp0 + l;                          // k' index
        int k = (kpr & 15) * 64 + (kpr >> 4);       // original k = h*64+i
        t[l][tx] = Wp[(size_t)k * 1024 + n0 + tx];
    }
    __syncthreads();
#pragma unroll
    for (int j = 0; j < 4; j++) {
        size_t o = (size_t)(n0 + ty + 8 * j) * 1024 + kp0 + tx;
        Bp[o] = __float2half_rn(t[tx][ty + 8 * j]);
    }
}

// ---------------------------------------------------------------------------
// Shared smem-layout constants (144-byte rows)
// ---------------------------------------------------------------------------
#define PADK 72                         // f16 elems per smem row (144 B)

// gemm3 (proj): BM=64, BN=64, 2 stages (R14/R12 schedule)
#define P_OFF_A  0
#define P_OFF_B  (64 * PADK)
#define P_STAGE  (128 * PADK)                 // 9216 halves
#define SM_BYTES_PROJ (2 * P_STAGE * 2)       // 36864

// gemm_out: BM=128, BN=64, 3-stage ring (R16 config)
#define O_OFF_A  0
#define O_OFF_B  (128 * PADK)
#define O_STAGE  (192 * PADK)                 // 13824 halves
#define SM_BYTES_OUT (3 * O_STAGE * 2)        // 82944

// ---- Projection GEMM (R14 config, R12 schedule): BM=64, 256 thr, 8 warps,
//      warp tile 16x32. A fp32 -> f16 on the fly, C written f16. -------------
struct PArgs {
    const float* A;
    const __half* B;
    const float* bias;
    __half* C;
};

__device__ __forceinline__
void gemm_proj_body(const PArgs& g, int ldc, int bm, __half* sm)
{
    const uint32_t sb = smem_u32(sm);
    const int tid  = threadIdx.x;
    const int lane = tid & 31, w = tid >> 5;
    const int gq = lane >> 2, tq = lane & 3;
    const int wm = (w >> 1) * 16, wn = (w & 1) * 32;

    const int rowA  = (lane & 15);
    const int colA8 = (lane >> 4) * 8;
    const int rowB  = ((lane >> 4) & 1) * 8 + (lane & 7);
    const int colB8 = ((lane >> 3) & 1) * 8;

    float acc[4][4];
#pragma unroll
    for (int nt = 0; nt < 4; nt++)
#pragma unroll
        for (int r = 0; r < 4; r++) acc[nt][r] = 0.f;

    float4 aR[4];

    auto load_A_regs = [&](int ch) {
        const int k0 = ch * 64;
#pragma unroll
        for (int p = 0; p < 4; p++) {
            int idx = p * 256 + tid;
            int r = idx >> 4, c4 = idx & 15;
            aR[p] = *(const float4*)&g.A[(size_t)(bm + r) * 1024 + k0 + c4 * 4];
        }
    };
    auto store_A = [&](int stg) {
        __half* A = sm + stg * P_STAGE + P_OFF_A;
#pragma unroll
        for (int p = 0; p < 4; p++) {
            int idx = p * 256 + tid;
            int r = idx >> 4, c4 = idx & 15;
            uint32_t h01 = f16pack(aR[p].x, aR[p].y);
            uint32_t h23 = f16pack(aR[p].z, aR[p].w);
            *(uint2*)(A + r * PADK + c4 * 4) = make_uint2(h01, h23);
        }
    };
    auto cp_B = [&](int ch, int stg) {
        const int k0 = ch * 64;
        const uint32_t bd = sb + (stg * P_STAGE + P_OFF_B) * 2;
#pragma unroll
        for (int p = 0; p < 2; p++) {
            int idx = p * 256 + tid;
            int r = idx >> 3, c8 = idx & 7;
            size_t off = (size_t)r * 1024 + k0 + c8 * 8;
            cp_async16(bd + (uint32_t)(r * 144 + c8 * 16), g.B + off);
        }
        CP_COMMIT();
    };
    auto do_mma = [&](int stg) {
        const uint32_t base = sb + (stg * P_STAGE) * 2;
        const uint32_t aB = base + P_OFF_A * 2;
        const uint32_t bB = base + P_OFF_B * 2;
#pragma unroll
        for (int ks = 0; ks < 4; ks++) {
            const int kk = ks * 16;
            uint32_t ah[4], bh[4][2];
            ldsm_x4(ah, aB + (uint32_t)((wm + rowA) * 144 + (kk + colA8) * 2));
#pragma unroll
            for (int p = 0; p < 2; p++) {
                uint32_t rh[4];
                ldsm_x4(rh, bB + (uint32_t)((wn + p * 16 + rowB) * 144 + (kk + colB8) * 2));
                bh[2 * p][0] = rh[0]; bh[2 * p][1] = rh[1];
                bh[2 * p + 1][0] = rh[2]; bh[2 * p + 1][1] = rh[3];
            }
#pragma unroll
            for (int nt = 0; nt < 4; nt++)
                mma_f16(acc[nt], ah, bh[nt]);
        }
    };

    // R12 schedule: issue next chunk's loads BEFORE this chunk's MMAs.
    load_A_regs(0);
    cp_B(0, 0);
    store_A(0);
    CP_WAIT0();
    __syncthreads();

    for (int ch = 0; ch < 16; ch++) {
        const int cur = ch & 1;
        if (ch < 15) {
            cp_B(ch + 1, cur ^ 1);
            load_A_regs(ch + 1);
        }
        do_mma(cur);
        if (ch < 15) {
            store_A(cur ^ 1);
            CP_WAIT0();
        }
        __syncthreads();
    }

    // epilogue: bias + f16 store
    const int row0 = bm + wm + gq;
#pragma unroll
    for (int nt = 0; nt < 4; nt++) {
        const int col = wn + nt * 8 + tq * 2;
        const float b0 = __ldg(&g.bias[col]);
        const float b1 = __ldg(&g.bias[col + 1]);
        *(uint32_t*)&g.C[(size_t)row0 * ldc + col] =
            f16pack(acc[nt][0] + b0, acc[nt][1] + b1);
        *(uint32_t*)&g.C[(size_t)(row0 + 8) * ldc + col] =
            f16pack(acc[nt][2] + b0, acc[nt][3] + b1);
    }
}

__global__ __launch_bounds__(256)
void gemm3_kernel(PArgs p0, PArgs p1, PArgs p2, int ldc)
{
    extern __shared__ __half sm[];
    PArgs p = (blockIdx.z == 0) ? p0 : (blockIdx.z == 1) ? p1 : p2;
    gemm_proj_body(p, ldc, blockIdx.x * 64, sm);
}

// ---- Output GEMM (R16 config): BM=128, 256 thr, 8 warps (4M x 2N),
//      warp tile 32x32, 3-stage cp.async ring. C fp32 + bias. ----------------
__global__ __launch_bounds__(256)
void gemm_out_kernel(const __half* __restrict__ A, const __half* __restrict__ B,
                     const float* __restrict__ bias, float* __restrict__ C, int ldc)
{
    extern __shared__ __half sm[];
    const uint32_t sb = smem_u32(sm);
    const int tid  = threadIdx.x;
    const int lane = tid & 31, w = tid >> 5;
    const int gq = lane >> 2, tq = lane & 3;
    const int wm = (w >> 1) * 32, wn = (w & 1) * 32;
    const int bm = blockIdx.x * 128, bn = blockIdx.y * 64;

    const int rowA  = (lane & 15);
    const int colA8 = (lane >> 4) * 8;
    const int rowB  = ((lane >> 4) & 1) * 8 + (lane & 7);
    const int colB8 = ((lane >> 3) & 1) * 8;

    float acc[2][4][4];
#pragma unroll
    for (int mt = 0; mt < 2; mt++)
#pragma unroll
        for (int nt = 0; nt < 4; nt++)
#pragma unroll
            for (int r = 0; r < 4; r++) acc[mt][nt][r] = 0.f;

    auto cp_stage = [&](int ch, int stg) {
        const int k0 = ch * 64;
        const uint32_t ad = sb + (stg * O_STAGE + O_OFF_A) * 2;
        const uint32_t bd = sb + (stg * O_STAGE + O_OFF_B) * 2;
#pragma unroll
        for (int p = 0; p < 4; p++) {       // A: 128 rows x 8 segs
            int idx = p * 256 + tid;
            int r = idx >> 3, c8 = idx & 7;
            cp_async16(ad + (uint32_t)(r * 144 + c8 * 16),
                       A + (size_t)(bm + r) * 1024 + k0 + c8 * 8);
        }
#pragma unroll
        for (int p = 0; p < 2; p++) {       // B: 64 rows x 8 segs
            int idx = p * 256 + tid;
            int r = idx >> 3, c8 = idx & 7;
            cp_async16(bd + (uint32_t)(r * 144 + c8 * 16),
                       B + (size_t)(bn + r) * 1024 + k0 + c8 * 8);
        }
        CP_COMMIT();
    };
    auto do_mma = [&](int stg) {
        const uint32_t base = sb + (stg * O_STAGE) * 2;
        const uint32_t aB = base + O_OFF_A * 2;
        const uint32_t bB = base + O_OFF_B * 2;
#pragma unroll
        for (int ks = 0; ks < 4; ks++) {
            const int kk = ks * 16;
            uint32_t ah[2][4], bh[4][2];
#pragma unroll
            for (int mt = 0; mt < 2; mt++)
                ldsm_x4(ah[mt], aB + (uint32_t)((wm + mt * 16 + rowA) * 144 + (kk + colA8) * 2));
#pragma unroll
            for (int p = 0; p < 2; p++) {
                uint32_t rh[4];
                ldsm_x4(rh, bB + (uint32_t)((wn + p * 16 + rowB) * 144 + (kk + colB8) * 2));
                bh[2 * p][0] = rh[0]; bh[2 * p][1] = rh[1];
                bh[2 * p + 1][0] = rh[2]; bh[2 * p + 1][1] = rh[3];
            }
#pragma unroll
            for (int mt = 0; mt < 2; mt++)
#pragma unroll
                for (int nt = 0; nt < 4; nt++)
                    mma_f16(acc[mt][nt], ah[mt], bh[nt]);
        }
    };

    // 3-stage ring: two chunks in flight at all times.
    cp_stage(0, 0);
    cp_stage(1, 1);

    for (int ch = 0; ch < 16; ch++) {
        CP_WAIT1();          // stage ch complete (<=1 group pending)
        __syncthreads();     // all warps done reading slot (ch-1)%3
        if (ch + 2 < 16) cp_stage(ch + 2, (ch + 2) % 3);
        else             CP_COMMIT();
        do_mma(ch % 3);
    }

#pragma unroll
    for (int mt = 0; mt < 2; mt++) {
        const int row0 = bm + wm + mt * 16 + gq;
#pragma unroll
        for (int nt = 0; nt < 4; nt++) {
            const int col = bn + wn + nt * 8 + tq * 2;
            const float b0 = __ldg(&bias[col]);
            const float b1 = __ldg(&bias[col + 1]);
            float2 v0 = make_float2(acc[mt][nt][0] + b0, acc[mt][nt][1] + b1);
            float2 v1 = make_float2(acc[mt][nt][2] + b0, acc[mt][nt][3] + b1);
            *(float2*)&C[(size_t)row0 * ldc + col]       = v0;
            *(float2*)&C[(size_t)(row0 + 8) * ldc + col] = v1;
        }
    }
}

// ---------------------------------------------------------------------------
// Tensor-core attention. One CTA (128 thr, 4 warps) per group n.
// Q/K/V stored ROW-MAJOR (coalesced); transposed fragments via ldmatrix.trans.
//   S = 0.25 * Qg^T Kg (64x64, K=16), masked, f16; X'[n][i*16+h] = (S @ Vg^T)[i,h]
// ---------------------------------------------------------------------------
#define AT_STR 72     // row stride in halves for all attn smem tiles

__global__ __launch_bounds__(128)
void attn_kernel(const __half* __restrict__ qp, const __half* __restrict__ kp,
                 const __half* __restrict__ vp, const int* __restrict__ mask,
                 __half* __restrict__ X)
{
    __shared__ __align__(16) __half Qs[16 * AT_STR];  // Qs[hh][i]
    __shared__ __align__(16) __half Ks[16 * AT_STR];  // Ks[hh][j]
    __shared__ __align__(16) __half Vs[16 * AT_STR];  // Vs[h][j]
    __shared__ __align__(16) __half Ss[64 * AT_STR];  // S f16, row-major [i][j]

    const int n = blockIdx.x, tid = threadIdx.x;
    const int lane = tid & 31, w = tid >> 5;
    const int gq = lane >> 2, tq = lane & 3;

    const uint4* qg = (const uint4*)(qp + (size_t)n * NHEAD * HEAD);
    const uint4* kg = (const uint4*)(kp + (size_t)n * NHEAD * HEAD);
    const uint4* vg = (const uint4*)(vp + (size_t)n * NHEAD * HEAD);

    // Row-major coalesced loads: thread tid -> row hh = tid>>3, cols c0..c0+7
    {
        const int hh = tid >> 3, c0 = (tid & 7) * 8;
        *(uint4*)&Qs[hh * AT_STR + c0] = qg[tid];
        *(uint4*)&Ks[hh * AT_STR + c0] = kg[tid];
        *(uint4*)&Vs[hh * AT_STR + c0] = vg[tid];
    }
    __syncthreads();

    // ---- Stage 1: S rows [16w, 16w+16), all 64 cols; K = 16 (one k-step)
    const int rTA = (lane & 7) + ((lane >> 4) & 1) * 8;   // hh
    const int cTA = ((lane >> 3) & 1) * 8;                // i offset within warp tile
    const uint32_t qsB = smem_u32(Qs), ksB = smem_u32(Ks);
    uint32_t aQ[4];
    ldsm_x4_t(aQ, qsB + (uint32_t)(rTA * AT_STR + 16 * w + cTA) * 2);

    const int rTB = (lane & 7) + ((lane >> 3) & 1) * 8;   // hh
    const int cTB = (lane >> 4) * 8;                      // j offset

    float sacc[8][4];
#pragma unroll
    for (int nt = 0; nt < 8; nt++)
#pragma unroll
        for (int r = 0; r < 4; r++) sacc[nt][r] = 0.f;

#pragma unroll
    for (int p = 0; p < 4; p++) {
        uint32_t rb[4];
        ldsm_x4_t(rb, ksB + (uint32_t)(rTB * AT_STR + p * 16 + cTB) * 2);
        uint32_t b0[2] = {rb[0], rb[1]}, b1[2] = {rb[2], rb[3]};
        mma_f16(sacc[2 * p],     aQ, b0);
        mma_f16(sacc[2 * p + 1], aQ, b1);
    }

    // scale + mask + f16 store to Ss
    const int i0 = 16 * w + gq;
#pragma unroll
    for (int nt = 0; nt < 8; nt++) {
        const int j0 = nt * 8 + tq * 2;
        int2 m0 = *(const int2*)&mask[i0 * 64 + j0];
        int2 m1 = *(const int2*)&mask[(i0 + 8) * 64 + j0];
        float s0 = sacc[nt][0] * 0.25f; if (m0.x == 0) s0 = -1e30f;
        float s1 = sacc[nt][1] * 0.25f; if (m0.y == 0) s1 = -1e30f;
        float s2 = sacc[nt][2] * 0.25f; if (m1.x == 0) s2 = -1e30f;
        float s3 = sacc[nt][3] * 0.25f; if (m1.y == 0) s3 = -1e30f;
        *(uint32_t*)&Ss[i0 * AT_STR + j0]       = f16pack(s0, s1);
        *(uint32_t*)&Ss[(i0 + 8) * AT_STR + j0] = f16pack(s2, s3);
    }
    __syncthreads();

    // ---- Stage 2: X rows [16w, 16w+16) x 16 heads; K = 64 (4 k-steps)
    const int rowA  = (lane & 15);
    const int colA8 = (lane >> 4) * 8;
    const int rowB  = ((lane >> 4) & 1) * 8 + (lane & 7);
    const int colB8 = ((lane >> 3) & 1) * 8;
    const uint32_t ssB = smem_u32(Ss), vsB = smem_u32(Vs);
    float xacc[2][4];
#pragma unroll
    for (int nt = 0; nt < 2; nt++)
#pragma unroll
        for (int r = 0; r < 4; r++) xacc[nt][r] = 0.f;

#pragma unroll
    for (int ks = 0; ks < 4; ks++) {
        uint32_t aS[4], rb[4];
        ldsm_x4(aS, ssB + (uint32_t)((16 * w + rowA) * AT_STR + ks * 16 + colA8) * 2);
        ldsm_x4(rb, vsB + (uint32_t)(rowB * AT_STR + ks * 16 + colB8) * 2);
        uint32_t b0[2] = {rb[0], rb[1]}, b1[2] = {rb[2], rb[3]};
        mma_f16(xacc[0], aS, b0);
        mma_f16(xacc[1], aS, b1);
    }

    // X'[n][i*16 + h], f16 (pairs over consecutive h)
    __half* Xn = X + (size_t)n * D_MODEL;
#pragma unroll
    for (int nt = 0; nt < 2; nt++) {
        const int h0 = nt * 8 + tq * 2;
        *(uint32_t*)&Xn[i0 * 16 + h0]       = f16pack(xacc[nt][0], xacc[nt][1]);
        *(uint32_t*)&Xn[(i0 + 8) * 16 + h0] = f16pack(xacc[nt][2], xacc[nt][3]);
    }
}

// ---------------------------------------------------------------------------
extern "C" void kernel_launch(void* const* d_in, const int* in_sizes, int n_in,
                              void* d_out, int out_size)
{
    const float* query = (const float*)d_in[0];
    const float* key   = (const float*)d_in[1];
    const float* value = (const float*)d_in[2];
    const int*   mask  = (const int*)  d_in[3];
    const float* Wq    = (const float*)d_in[4];
    const float* bq    = (const float*)d_in[5];
    const float* Wk    = (const float*)d_in[6];
    const float* bk    = (const float*)d_in[7];
    const float* Wv    = (const float*)d_in[8];
    const float* bv    = (const float*)d_in[9];
    const float* Wp    = (const float*)d_in[10];
    const float* bp    = (const float*)d_in[11];
    float* out = (float*)d_out;

    __half *qp, *kp, *vp, *xg, *wq, *wk, *wv, *wp;
    cudaGetSymbolAddress((void**)&qp, g_qp);
    cudaGetSymbolAddress((void**)&kp, g_kp);
    cudaGetSymbolAddress((void**)&vp, g_vp);
    cudaGetSymbolAddress((void**)&xg, g_x);
    cudaGetSymbolAddress((void**)&wq, g_wq);
    cudaGetSymbolAddress((void**)&wk, g_wk);
    cudaGetSymbolAddress((void**)&wv, g_wv);
    cudaGetSymbolAddress((void**)&wp, g_wp);

    cudaFuncSetAttribute(gemm3_kernel, cudaFuncAttributeMaxDynamicSharedMemorySize, SM_BYTES_PROJ);
    cudaFuncSetAttribute(gemm_out_kernel, cudaFuncAttributeMaxDynamicSharedMemorySize, SM_BYTES_OUT);

    // Weight prep: tight merged grid (y<32: Wp, y>=32: Q/K/V tiles)
    wprep_all_kernel<<<dim3(32, 38), dim3(32, 8)>>>(Wq, wq, Wk, wk, Wv, wv, Wp, wp);

    // Merged projections: (16384 x 1024) @ (1024 x 64) + bias, x3 -> f16
    PArgs pq = {query, wq, bq, qp};
    PArgs pk = {key,   wk, bk, kp};
    PArgs pv = {value, wv, bv, vp};
    gemm3_kernel<<<dim3(ROWS / 64, 1, 3), 256, SM_BYTES_PROJ>>>(pq, pk, pv, HEAD);

    // Attention middle stage -> X' f16 [n][i*16+h]
    attn_kernel<<<NGRP, 128>>>(qp, kp, vp, mask, xg);

    // Output projection: (1024 x 1024) @ (1024 x 1024) + bias (fp32 out)
    gemm_out_kernel<<<dim3(NGRP / 128, D_MODEL / 64), 256, SM_BYTES_OUT>>>(xg, wp, bp, out, D_MODEL);
}